// round 7
// baseline (speedup 1.0000x reference)
#include <cuda_runtime.h>
#include <cstdint>

// Problem constants
#define QS   512
#define BATCH 8
#define CDIM 1024
#define HEADS 16
#define HC   64
#define MMEM 1536

#define NEG_INF (__int_as_float(0xff800000))

// Scratch (device globals — no allocation allowed)
__device__ float g_qbuf[QS * BATCH * CDIM];
__device__ float g_kbuf[QS * BATCH * CDIM];
__device__ float g_vbuf[QS * BATCH * CDIM];
__device__ float g_xbuf[QS * BATCH * CDIM];

// ---------------------------------------------------------------------------
// GEMM: out[m,n] = sum_k A[m,k] * W[n,k] + bias[n]
// A: [4096,1024] row-major, W: [1024,1024] row-major (TN GEMM, K contiguous).
// Tile 128x128x16, 256 threads, 8x8 per-thread microtile, fp32.
// Up to 3 weight sets selected by blockIdx.y/8 (fused QKV).
// ---------------------------------------------------------------------------
struct GemmSet { const float* W; const float* bias; float* out; };

__global__ __launch_bounds__(256) void gemm_tn_multi(
    const float* __restrict__ A, GemmSet s0, GemmSet s1, GemmSet s2)
{
    constexpr int BM = 128, BN = 128, BK = 16, K = 1024;
    __shared__ float As[BK][BM + 4];
    __shared__ float Bs[BK][BN + 4];

    const int mat = blockIdx.y >> 3;          // 8 column-blocks per matrix
    const int bn  = blockIdx.y & 7;
    GemmSet g = (mat == 0) ? s0 : (mat == 1) ? s1 : s2;

    const int m0 = blockIdx.x * BM;
    const int n0 = bn * BN;
    const int tid = threadIdx.x;
    const int tm = (tid >> 4) * 8;            // 16x16 thread grid
    const int tn = (tid & 15) * 8;

    float acc[8][8];
#pragma unroll
    for (int i = 0; i < 8; i++)
#pragma unroll
        for (int j = 0; j < 8; j++) acc[i][j] = 0.f;

    const float* Ag = A   + (size_t)m0 * K;
    const float* Wg = g.W + (size_t)n0 * K;

    for (int k0 = 0; k0 < K; k0 += BK) {
        // 128 rows x 16 k-floats per operand = 512 float4; 2 per thread each.
#pragma unroll
        for (int i = 0; i < 2; i++) {
            int idx = tid + i * 256;
            int row = idx >> 2;
            int kq  = (idx & 3) << 2;
            float4 av = *(const float4*)(Ag + (size_t)row * K + k0 + kq);
            As[kq + 0][row] = av.x; As[kq + 1][row] = av.y;
            As[kq + 2][row] = av.z; As[kq + 3][row] = av.w;
            float4 bv = *(const float4*)(Wg + (size_t)row * K + k0 + kq);
            Bs[kq + 0][row] = bv.x; Bs[kq + 1][row] = bv.y;
            Bs[kq + 2][row] = bv.z; Bs[kq + 3][row] = bv.w;
        }
        __syncthreads();

#pragma unroll
        for (int kk = 0; kk < BK; kk++) {
            float a[8], b[8];
            *(float4*)&a[0] = *(const float4*)&As[kk][tm];
            *(float4*)&a[4] = *(const float4*)&As[kk][tm + 4];
            *(float4*)&b[0] = *(const float4*)&Bs[kk][tn];
            *(float4*)&b[4] = *(const float4*)&Bs[kk][tn + 4];
#pragma unroll
            for (int i = 0; i < 8; i++)
#pragma unroll
                for (int j = 0; j < 8; j++)
                    acc[i][j] += a[i] * b[j];
        }
        __syncthreads();
    }

    float bias[8];
    *(float4*)&bias[0] = *(const float4*)(g.bias + n0 + tn);
    *(float4*)&bias[4] = *(const float4*)(g.bias + n0 + tn + 4);

#pragma unroll
    for (int i = 0; i < 8; i++) {
        float4 r0, r1;
        r0.x = acc[i][0] + bias[0]; r0.y = acc[i][1] + bias[1];
        r0.z = acc[i][2] + bias[2]; r0.w = acc[i][3] + bias[3];
        r1.x = acc[i][4] + bias[4]; r1.y = acc[i][5] + bias[5];
        r1.z = acc[i][6] + bias[6]; r1.w = acc[i][7] + bias[7];
        float* op = g.out + (size_t)(m0 + tm + i) * 1024 + n0 + tn;
        *(float4*)op       = r0;
        *(float4*)(op + 4) = r1;
    }
}

// ---------------------------------------------------------------------------
// Flash attention over combined memory + new KV.
// Key t in [0,L): K/V from memory_kv[t,b,h,:64 / 64:128]
// Key t in [L,L+pad): K/V from projected k/v at row (t-L), user mask applies
// Key t >= L+pad: fully masked (never touched).
// Block = (q-tile of 128 rows, one (b,h)); thread = one query row.
// ---------------------------------------------------------------------------
__global__ __launch_bounds__(128) void attn_kernel(
    const float* __restrict__ Q, const float* __restrict__ Kb,
    const float* __restrict__ Vb, const float* __restrict__ memkv,
    const int* __restrict__ memlen, const int* __restrict__ pad,
    const unsigned char* __restrict__ mask, float* __restrict__ X)
{
    constexpr int KT = 32;
    const int bh = blockIdx.y;
    const int b = bh >> 4;
    const int h = bh & 15;
    const int s = blockIdx.x * 128 + threadIdx.x;

    const int L = memlen[b];
    const int P = pad[b];
    const int Teff = L + P;

    float q[HC];
    const float* qp = Q + ((size_t)s * BATCH + b) * CDIM + h * HC;
#pragma unroll
    for (int c4 = 0; c4 < 16; c4++)
        *(float4*)&q[c4 * 4] = *(const float4*)(qp + c4 * 4);

    float mrun = NEG_INF, lrun = 0.f;
    float o[HC];
#pragma unroll
    for (int c = 0; c < HC; c++) o[c] = 0.f;

    __shared__ float Ks[KT][HC];
    __shared__ float Vs[KT][HC];

    for (int t0 = 0; t0 < Teff; t0 += KT) {
        // Cooperative gather of 32 keys+values (64 floats each): 512 float4,
        // 4 per thread.
#pragma unroll
        for (int i = 0; i < 4; i++) {
            int idx = threadIdx.x + i * 128;
            int j   = idx >> 4;
            int c4  = (idx & 15) << 2;
            int t   = t0 + j;
            float4 kv = make_float4(0.f, 0.f, 0.f, 0.f);
            float4 vv = make_float4(0.f, 0.f, 0.f, 0.f);
            if (t < L) {
                const float* p = memkv + (((size_t)t * BATCH + b) * HEADS + h) * (2 * HC);
                kv = *(const float4*)(p + c4);
                vv = *(const float4*)(p + HC + c4);
            } else if (t < Teff) {
                size_t base = ((size_t)(t - L) * BATCH + b) * CDIM + h * HC + c4;
                kv = *(const float4*)(Kb + base);
                vv = *(const float4*)(Vb + base);
            }
            *(float4*)&Ks[j][c4] = kv;
            *(float4*)&Vs[j][c4] = vv;
        }
        __syncthreads();

        // Scores: q . K_j  (broadcast shared reads, 4-way ILP)
        float sc[KT];
#pragma unroll
        for (int j = 0; j < KT; j++) {
            float a0 = 0.f, a1 = 0.f, a2 = 0.f, a3 = 0.f;
#pragma unroll
            for (int c4 = 0; c4 < 16; c4++) {
                float4 kv = *(const float4*)&Ks[j][c4 * 4];
                a0 += q[c4 * 4 + 0] * kv.x;
                a1 += q[c4 * 4 + 1] * kv.y;
                a2 += q[c4 * 4 + 2] * kv.z;
                a3 += q[c4 * 4 + 3] * kv.w;
            }
            sc[j] = (a0 + a1) + (a2 + a3);
        }

        // Scale + mask
        float tmax = NEG_INF;
#pragma unroll
        for (int j = 0; j < KT; j++) {
            int t = t0 + j;
            float v = sc[j] * 0.125f;  // 1/sqrt(HC)
            bool valid = (t < Teff);
            if (valid && t >= L) {
                if (mask[((size_t)s * QS + (t - L)) * BATCH + b]) valid = false;
            }
            sc[j] = valid ? v : NEG_INF;
            tmax = fmaxf(tmax, sc[j]);
        }

        float mn = fmaxf(mrun, tmax);
        if (mn > NEG_INF) {
            float corr = __expf(mrun - mn);  // exp(-inf - finite) = 0
            float ls = 0.f;
#pragma unroll
            for (int j = 0; j < KT; j++) {
                sc[j] = __expf(sc[j] - mn);
                ls += sc[j];
            }
            lrun = lrun * corr + ls;
#pragma unroll
            for (int c = 0; c < HC; c++) o[c] *= corr;
#pragma unroll
            for (int j = 0; j < KT; j++) {
                float p = sc[j];
#pragma unroll
                for (int c4 = 0; c4 < 16; c4++) {
                    float4 vv = *(const float4*)&Vs[j][c4 * 4];
                    o[c4 * 4 + 0] += p * vv.x;
                    o[c4 * 4 + 1] += p * vv.y;
                    o[c4 * 4 + 2] += p * vv.z;
                    o[c4 * 4 + 3] += p * vv.w;
                }
            }
            mrun = mn;
        }
        __syncthreads();
    }

    // nan_to_num: all-masked / empty rows -> 0
    const float inv = (lrun > 0.f) ? (1.f / lrun) : 0.f;
    float* xp = X + ((size_t)s * BATCH + b) * CDIM + h * HC;
#pragma unroll
    for (int c4 = 0; c4 < 16; c4++) {
        float4 r;
        r.x = o[c4 * 4 + 0] * inv;
        r.y = o[c4 * 4 + 1] * inv;
        r.z = o[c4 * 4 + 2] * inv;
        r.w = o[c4 * 4 + 3] * inv;
        *(float4*)(xp + c4 * 4) = r;
    }
}

// ---------------------------------------------------------------------------
// Launch: QKV GEMM (fused) -> attention -> output GEMM. Graph-capturable.
// Input order per metadata: xq, pad, mask, memory_length, memory_kv,
//                           Wq, bq, Wk, bk, Wv, bv, Wo, bo
// ---------------------------------------------------------------------------
extern "C" void kernel_launch(void* const* d_in, const int* in_sizes, int n_in,
                              void* d_out, int out_size)
{
    const float*         xq     = (const float*)d_in[0];
    const int*           padv   = (const int*)d_in[1];
    const unsigned char* mask   = (const unsigned char*)d_in[2];
    const int*           memlen = (const int*)d_in[3];
    const float*         memkv  = (const float*)d_in[4];
    const float*         Wq     = (const float*)d_in[5];
    const float*         bq     = (const float*)d_in[6];
    const float*         Wk     = (const float*)d_in[7];
    const float*         bk     = (const float*)d_in[8];
    const float*         Wv     = (const float*)d_in[9];
    const float*         bv     = (const float*)d_in[10];
    const float*         Wo     = (const float*)d_in[11];
    const float*         bo     = (const float*)d_in[12];
    float*               out    = (float*)d_out;

    float *qb, *kb, *vb, *xb;
    cudaGetSymbolAddress((void**)&qb, g_qbuf);
    cudaGetSymbolAddress((void**)&kb, g_kbuf);
    cudaGetSymbolAddress((void**)&vb, g_vbuf);
    cudaGetSymbolAddress((void**)&xb, g_xbuf);

    GemmSet sq{Wq, bq, qb};
    GemmSet sk{Wk, bk, kb};
    GemmSet sv{Wv, bv, vb};
    GemmSet so{Wo, bo, out};

    // Fused QKV projection: M=4096, N=3*1024, K=1024
    gemm_tn_multi<<<dim3(32, 24), 256>>>(xq, sq, sk, sv);

    // Attention: 4 q-tiles x (B*H=128)
    attn_kernel<<<dim3(4, 128), 128>>>(qb, kb, vb, memkv, memlen, padv, mask, xb);

    // Output projection: M=4096, N=1024, K=1024 (only set 0 used, grid.y=8)
    gemm_tn_multi<<<dim3(32, 8), 256>>>(xb, so, so, so);
}

// round 12
// speedup vs baseline: 1.5228x; 1.5228x over previous
#include <cuda_runtime.h>
#include <cstdint>

// Problem constants
#define QS   512
#define BATCH 8
#define CDIM 1024
#define HEADS 16
#define HC   64
#define MMEM 1536

#define NEG_INF (__int_as_float(0xff800000))

// Scratch (device globals — no allocation allowed)
__device__ float g_qbuf[QS * BATCH * CDIM];
__device__ float g_kbuf[QS * BATCH * CDIM];
__device__ float g_vbuf[QS * BATCH * CDIM];
__device__ float g_xbuf[QS * BATCH * CDIM];

struct GemmSet { const float* W; const float* bias; float* out; };

// ---------------------------------------------------------------------------
// TF32 tensor-core GEMM: out[m,n] = sum_k A[m,k] * W[n,k] + bias[n]
// A: [4096,1024] row-major, W: [1024,1024] row-major (TN; K contiguous both).
// Tile 128x128x32, 256 threads = 8 warps (2 along M x 4 along N),
// warp tile 64x32 via mma.sync.m16n8k8 tf32 (4 m-frags x 4 n-frags).
// Up to 3 weight sets selected by blockIdx.y/8 (fused QKV).
// ---------------------------------------------------------------------------
__global__ __launch_bounds__(256, 2) void gemm_tf32_multi(
    const float* __restrict__ A, GemmSet s0, GemmSet s1, GemmSet s2)
{
    constexpr int K = 1024, BK = 32;
    // [row][36]: 36 mod 32 = 4 -> fragment loads (quad stride 4 banks) conflict-free
    __shared__ __align__(16) uint32_t As[128][36];
    __shared__ __align__(16) uint32_t Bs[128][36];

    const int mat = blockIdx.y >> 3;          // 8 column-blocks per matrix
    const int bn  = blockIdx.y & 7;
    GemmSet g = (mat == 0) ? s0 : (mat == 1) ? s1 : s2;

    const int m0 = blockIdx.x * 128;
    const int n0 = bn * 128;
    const int tid  = threadIdx.x;
    const int warp = tid >> 5;
    const int lane = tid & 31;
    const int wm = (warp >> 2) * 64;          // warp M offset (2 warps)
    const int wn = (warp & 3) * 32;           // warp N offset (4 warps)
    const int lr = lane >> 2;                 // 0..7
    const int lc = lane & 3;                  // 0..3

    float acc[4][4][4];                       // [mi][ni][c0..c3]
#pragma unroll
    for (int mi = 0; mi < 4; mi++)
#pragma unroll
        for (int ni = 0; ni < 4; ni++)
#pragma unroll
            for (int c = 0; c < 4; c++) acc[mi][ni][c] = 0.f;

    const float* Ag = A   + (size_t)m0 * K;
    const float* Wg = g.W + (size_t)n0 * K;

    for (int k0 = 0; k0 < K; k0 += BK) {
        // Stage 128x32 of A and W: 1024 float4 each, 4 per thread per operand.
        // Convert fp32 -> tf32 (rna) while staging.
#pragma unroll
        for (int i = 0; i < 4; i++) {
            int idx = tid + i * 256;
            int row = idx >> 3;
            int kq  = (idx & 7) << 2;
            float4 av = *(const float4*)(Ag + (size_t)row * K + k0 + kq);
            uint4 au;
            asm("cvt.rna.tf32.f32 %0, %1;" : "=r"(au.x) : "f"(av.x));
            asm("cvt.rna.tf32.f32 %0, %1;" : "=r"(au.y) : "f"(av.y));
            asm("cvt.rna.tf32.f32 %0, %1;" : "=r"(au.z) : "f"(av.z));
            asm("cvt.rna.tf32.f32 %0, %1;" : "=r"(au.w) : "f"(av.w));
            *(uint4*)&As[row][kq] = au;
            float4 wv = *(const float4*)(Wg + (size_t)row * K + k0 + kq);
            uint4 wu;
            asm("cvt.rna.tf32.f32 %0, %1;" : "=r"(wu.x) : "f"(wv.x));
            asm("cvt.rna.tf32.f32 %0, %1;" : "=r"(wu.y) : "f"(wv.y));
            asm("cvt.rna.tf32.f32 %0, %1;" : "=r"(wu.z) : "f"(wv.z));
            asm("cvt.rna.tf32.f32 %0, %1;" : "=r"(wu.w) : "f"(wv.w));
            *(uint4*)&Bs[row][kq] = wu;
        }
        __syncthreads();

#pragma unroll
        for (int kk = 0; kk < BK; kk += 8) {
            uint32_t af[4][4], bf[4][2];
#pragma unroll
            for (int mi = 0; mi < 4; mi++) {
                int r = wm + mi * 16 + lr;
                af[mi][0] = As[r][kk + lc];          // (row,     k)
                af[mi][1] = As[r + 8][kk + lc];      // (row + 8, k)
                af[mi][2] = As[r][kk + lc + 4];      // (row,     k+4)
                af[mi][3] = As[r + 8][kk + lc + 4];  // (row + 8, k+4)
            }
#pragma unroll
            for (int ni = 0; ni < 4; ni++) {
                int n = wn + ni * 8 + lr;
                bf[ni][0] = Bs[n][kk + lc];          // (k,   n)
                bf[ni][1] = Bs[n][kk + lc + 4];      // (k+4, n)
            }
#pragma unroll
            for (int mi = 0; mi < 4; mi++)
#pragma unroll
                for (int ni = 0; ni < 4; ni++) {
                    asm volatile(
                        "mma.sync.aligned.m16n8k8.row.col.f32.tf32.tf32.f32 "
                        "{%0,%1,%2,%3}, {%4,%5,%6,%7}, {%8,%9}, {%0,%1,%2,%3};"
                        : "+f"(acc[mi][ni][0]), "+f"(acc[mi][ni][1]),
                          "+f"(acc[mi][ni][2]), "+f"(acc[mi][ni][3])
                        : "r"(af[mi][0]), "r"(af[mi][1]),
                          "r"(af[mi][2]), "r"(af[mi][3]),
                          "r"(bf[ni][0]), "r"(bf[ni][1]));
                }
        }
        __syncthreads();
    }

    // Epilogue: c0/c1 at (row, 2*lc), (row, 2*lc+1); c2/c3 at row+8.
#pragma unroll
    for (int ni = 0; ni < 4; ni++) {
        int c = n0 + wn + ni * 8 + 2 * lc;
        float bias0 = g.bias[c];
        float bias1 = g.bias[c + 1];
#pragma unroll
        for (int mi = 0; mi < 4; mi++) {
            int r = m0 + wm + mi * 16 + lr;
            float2 v0 = make_float2(acc[mi][ni][0] + bias0, acc[mi][ni][1] + bias1);
            float2 v1 = make_float2(acc[mi][ni][2] + bias0, acc[mi][ni][3] + bias1);
            *(float2*)(g.out + (size_t)r * 1024 + c)       = v0;
            *(float2*)(g.out + (size_t)(r + 8) * 1024 + c) = v1;
        }
    }
}

// ---------------------------------------------------------------------------
// Flash attention over combined memory + new KV (unchanged this round).
// ---------------------------------------------------------------------------
__global__ __launch_bounds__(128) void attn_kernel(
    const float* __restrict__ Q, const float* __restrict__ Kb,
    const float* __restrict__ Vb, const float* __restrict__ memkv,
    const int* __restrict__ memlen, const int* __restrict__ pad,
    const unsigned char* __restrict__ mask, float* __restrict__ X)
{
    constexpr int KT = 32;
    const int bh = blockIdx.y;
    const int b = bh >> 4;
    const int h = bh & 15;
    const int s = blockIdx.x * 128 + threadIdx.x;

    const int L = memlen[b];
    const int P = pad[b];
    const int Teff = L + P;

    float q[HC];
    const float* qp = Q + ((size_t)s * BATCH + b) * CDIM + h * HC;
#pragma unroll
    for (int c4 = 0; c4 < 16; c4++)
        *(float4*)&q[c4 * 4] = *(const float4*)(qp + c4 * 4);

    float mrun = NEG_INF, lrun = 0.f;
    float o[HC];
#pragma unroll
    for (int c = 0; c < HC; c++) o[c] = 0.f;

    __shared__ float Ks[KT][HC];
    __shared__ float Vs[KT][HC];

    for (int t0 = 0; t0 < Teff; t0 += KT) {
#pragma unroll
        for (int i = 0; i < 4; i++) {
            int idx = threadIdx.x + i * 128;
            int j   = idx >> 4;
            int c4  = (idx & 15) << 2;
            int t   = t0 + j;
            float4 kv = make_float4(0.f, 0.f, 0.f, 0.f);
            float4 vv = make_float4(0.f, 0.f, 0.f, 0.f);
            if (t < L) {
                const float* p = memkv + (((size_t)t * BATCH + b) * HEADS + h) * (2 * HC);
                kv = *(const float4*)(p + c4);
                vv = *(const float4*)(p + HC + c4);
            } else if (t < Teff) {
                size_t base = ((size_t)(t - L) * BATCH + b) * CDIM + h * HC + c4;
                kv = *(const float4*)(Kb + base);
                vv = *(const float4*)(Vb + base);
            }
            *(float4*)&Ks[j][c4] = kv;
            *(float4*)&Vs[j][c4] = vv;
        }
        __syncthreads();

        float sc[KT];
#pragma unroll
        for (int j = 0; j < KT; j++) {
            float a0 = 0.f, a1 = 0.f, a2 = 0.f, a3 = 0.f;
#pragma unroll
            for (int c4 = 0; c4 < 16; c4++) {
                float4 kv = *(const float4*)&Ks[j][c4 * 4];
                a0 += q[c4 * 4 + 0] * kv.x;
                a1 += q[c4 * 4 + 1] * kv.y;
                a2 += q[c4 * 4 + 2] * kv.z;
                a3 += q[c4 * 4 + 3] * kv.w;
            }
            sc[j] = (a0 + a1) + (a2 + a3);
        }

        float tmax = NEG_INF;
#pragma unroll
        for (int j = 0; j < KT; j++) {
            int t = t0 + j;
            float v = sc[j] * 0.125f;  // 1/sqrt(HC)
            bool valid = (t < Teff);
            if (valid && t >= L) {
                if (mask[((size_t)s * QS + (t - L)) * BATCH + b]) valid = false;
            }
            sc[j] = valid ? v : NEG_INF;
            tmax = fmaxf(tmax, sc[j]);
        }

        float mn = fmaxf(mrun, tmax);
        if (mn > NEG_INF) {
            float corr = __expf(mrun - mn);
            float ls = 0.f;
#pragma unroll
            for (int j = 0; j < KT; j++) {
                sc[j] = __expf(sc[j] - mn);
                ls += sc[j];
            }
            lrun = lrun * corr + ls;
#pragma unroll
            for (int c = 0; c < HC; c++) o[c] *= corr;
#pragma unroll
            for (int j = 0; j < KT; j++) {
                float p = sc[j];
#pragma unroll
                for (int c4 = 0; c4 < 16; c4++) {
                    float4 vv = *(const float4*)&Vs[j][c4 * 4];
                    o[c4 * 4 + 0] += p * vv.x;
                    o[c4 * 4 + 1] += p * vv.y;
                    o[c4 * 4 + 2] += p * vv.z;
                    o[c4 * 4 + 3] += p * vv.w;
                }
            }
            mrun = mn;
        }
        __syncthreads();
    }

    const float inv = (lrun > 0.f) ? (1.f / lrun) : 0.f;
    float* xp = X + ((size_t)s * BATCH + b) * CDIM + h * HC;
#pragma unroll
    for (int c4 = 0; c4 < 16; c4++) {
        float4 r;
        r.x = o[c4 * 4 + 0] * inv;
        r.y = o[c4 * 4 + 1] * inv;
        r.z = o[c4 * 4 + 2] * inv;
        r.w = o[c4 * 4 + 3] * inv;
        *(float4*)(xp + c4 * 4) = r;
    }
}

// ---------------------------------------------------------------------------
// Launch: QKV GEMM (fused, tf32 MMA) -> attention -> output GEMM (tf32 MMA).
// Input order: xq, pad, mask, memory_length, memory_kv,
//              Wq, bq, Wk, bk, Wv, bv, Wo, bo
// ---------------------------------------------------------------------------
extern "C" void kernel_launch(void* const* d_in, const int* in_sizes, int n_in,
                              void* d_out, int out_size)
{
    const float*         xq     = (const float*)d_in[0];
    const int*           padv   = (const int*)d_in[1];
    const unsigned char* mask   = (const unsigned char*)d_in[2];
    const int*           memlen = (const int*)d_in[3];
    const float*         memkv  = (const float*)d_in[4];
    const float*         Wq     = (const float*)d_in[5];
    const float*         bq     = (const float*)d_in[6];
    const float*         Wk     = (const float*)d_in[7];
    const float*         bk     = (const float*)d_in[8];
    const float*         Wv     = (const float*)d_in[9];
    const float*         bv     = (const float*)d_in[10];
    const float*         Wo     = (const float*)d_in[11];
    const float*         bo     = (const float*)d_in[12];
    float*               out    = (float*)d_out;

    float *qb, *kb, *vb, *xb;
    cudaGetSymbolAddress((void**)&qb, g_qbuf);
    cudaGetSymbolAddress((void**)&kb, g_kbuf);
    cudaGetSymbolAddress((void**)&vb, g_vbuf);
    cudaGetSymbolAddress((void**)&xb, g_xbuf);

    GemmSet sq{Wq, bq, qb};
    GemmSet sk{Wk, bk, kb};
    GemmSet sv{Wv, bv, vb};
    GemmSet so{Wo, bo, out};

    // Fused QKV projection: M=4096, N=3*1024, K=1024 (tf32 tensor cores)
    gemm_tf32_multi<<<dim3(32, 24), 256>>>(xq, sq, sk, sv);

    // Attention: 4 q-tiles x (B*H=128)
    attn_kernel<<<dim3(4, 128), 128>>>(qb, kb, vb, memkv, memlen, padv, mask, xb);

    // Output projection: M=4096, N=1024, K=1024
    gemm_tf32_multi<<<dim3(32, 8), 256>>>(xb, so, so, so);
}

// round 13
// speedup vs baseline: 2.8296x; 1.8582x over previous
#include <cuda_runtime.h>
#include <cstdint>

// Problem constants
#define QS    512
#define BATCH 8
#define CDIM  1024
#define HEADS 16
#define HC    64
#define MMEM  1536

#define NEG_INF (__int_as_float(0xff800000))

// Scratch (device globals — no allocation allowed)
__device__ float g_qbuf[QS * BATCH * CDIM];
__device__ float g_kbuf[QS * BATCH * CDIM];
__device__ float g_vbuf[QS * BATCH * CDIM];
__device__ float g_xbuf[QS * BATCH * CDIM];

struct GemmSet { const float* W; const float* bias; float* out; };

__device__ __forceinline__ uint32_t f2tf32(float x) {
    uint32_t u;
    asm("cvt.rna.tf32.f32 %0, %1;" : "=r"(u) : "f"(x));
    return u;
}

// ---------------------------------------------------------------------------
// TF32 tensor-core GEMM: out[m,n] = sum_k A[m,k] * W[n,k] + bias[n]
// (unchanged from round 7 — 205us QKV, ~70us O-proj)
// ---------------------------------------------------------------------------
__global__ __launch_bounds__(256, 2) void gemm_tf32_multi(
    const float* __restrict__ A, GemmSet s0, GemmSet s1, GemmSet s2)
{
    constexpr int K = 1024, BK = 32;
    __shared__ __align__(16) uint32_t As[128][36];
    __shared__ __align__(16) uint32_t Bs[128][36];

    const int mat = blockIdx.y >> 3;
    const int bn  = blockIdx.y & 7;
    GemmSet g = (mat == 0) ? s0 : (mat == 1) ? s1 : s2;

    const int m0 = blockIdx.x * 128;
    const int n0 = bn * 128;
    const int tid  = threadIdx.x;
    const int warp = tid >> 5;
    const int lane = tid & 31;
    const int wm = (warp >> 2) * 64;
    const int wn = (warp & 3) * 32;
    const int lr = lane >> 2;
    const int lc = lane & 3;

    float acc[4][4][4];
#pragma unroll
    for (int mi = 0; mi < 4; mi++)
#pragma unroll
        for (int ni = 0; ni < 4; ni++)
#pragma unroll
            for (int c = 0; c < 4; c++) acc[mi][ni][c] = 0.f;

    const float* Ag = A   + (size_t)m0 * K;
    const float* Wg = g.W + (size_t)n0 * K;

    for (int k0 = 0; k0 < K; k0 += BK) {
#pragma unroll
        for (int i = 0; i < 4; i++) {
            int idx = tid + i * 256;
            int row = idx >> 3;
            int kq  = (idx & 7) << 2;
            float4 av = *(const float4*)(Ag + (size_t)row * K + k0 + kq);
            uint4 au = make_uint4(f2tf32(av.x), f2tf32(av.y), f2tf32(av.z), f2tf32(av.w));
            *(uint4*)&As[row][kq] = au;
            float4 wv = *(const float4*)(Wg + (size_t)row * K + k0 + kq);
            uint4 wu = make_uint4(f2tf32(wv.x), f2tf32(wv.y), f2tf32(wv.z), f2tf32(wv.w));
            *(uint4*)&Bs[row][kq] = wu;
        }
        __syncthreads();

#pragma unroll
        for (int kk = 0; kk < BK; kk += 8) {
            uint32_t af[4][4], bf[4][2];
#pragma unroll
            for (int mi = 0; mi < 4; mi++) {
                int r = wm + mi * 16 + lr;
                af[mi][0] = As[r][kk + lc];
                af[mi][1] = As[r + 8][kk + lc];
                af[mi][2] = As[r][kk + lc + 4];
                af[mi][3] = As[r + 8][kk + lc + 4];
            }
#pragma unroll
            for (int ni = 0; ni < 4; ni++) {
                int n = wn + ni * 8 + lr;
                bf[ni][0] = Bs[n][kk + lc];
                bf[ni][1] = Bs[n][kk + lc + 4];
            }
#pragma unroll
            for (int mi = 0; mi < 4; mi++)
#pragma unroll
                for (int ni = 0; ni < 4; ni++) {
                    asm volatile(
                        "mma.sync.aligned.m16n8k8.row.col.f32.tf32.tf32.f32 "
                        "{%0,%1,%2,%3}, {%4,%5,%6,%7}, {%8,%9}, {%0,%1,%2,%3};"
                        : "+f"(acc[mi][ni][0]), "+f"(acc[mi][ni][1]),
                          "+f"(acc[mi][ni][2]), "+f"(acc[mi][ni][3])
                        : "r"(af[mi][0]), "r"(af[mi][1]),
                          "r"(af[mi][2]), "r"(af[mi][3]),
                          "r"(bf[ni][0]), "r"(bf[ni][1]));
                }
        }
        __syncthreads();
    }

#pragma unroll
    for (int ni = 0; ni < 4; ni++) {
        int c = n0 + wn + ni * 8 + 2 * lc;
        float bias0 = g.bias[c];
        float bias1 = g.bias[c + 1];
#pragma unroll
        for (int mi = 0; mi < 4; mi++) {
            int r = m0 + wm + mi * 16 + lr;
            float2 v0 = make_float2(acc[mi][ni][0] + bias0, acc[mi][ni][1] + bias1);
            float2 v1 = make_float2(acc[mi][ni][2] + bias0, acc[mi][ni][3] + bias1);
            *(float2*)(g.out + (size_t)r * 1024 + c)       = v0;
            *(float2*)(g.out + (size_t)(r + 8) * 1024 + c) = v1;
        }
    }
}

// ---------------------------------------------------------------------------
// Tensor-core flash attention.
// Block: 128 q-rows x one (b,h). 8 warps, each owns a 16-row q-tile.
// Key tile KT=32 staged to shared (tf32) cooperatively each iteration.
// S = Q K^T via mma.m16n8k8.tf32; online softmax in C-fragment layout
// (row reductions via shfl over the lane%4 quad); P round-trips through a
// per-warp smem buffer to become A-fragments; O = P V accumulated by mma.
// Shared strides (68 / 72 / 36 words) make all fragment LDS conflict-free.
// ---------------------------------------------------------------------------
__global__ __launch_bounds__(256, 2) void attn_mma(
    const float* __restrict__ Q, const float* __restrict__ Kb,
    const float* __restrict__ Vb, const float* __restrict__ memkv,
    const int* __restrict__ memlen, const int* __restrict__ pad,
    const unsigned char* __restrict__ mask, float* __restrict__ X)
{
    constexpr int KT = 32;
    __shared__ uint32_t Ks[KT][68];        // [key][col]  tf32
    __shared__ uint32_t Vs[KT][72];        // [key][col]  tf32
    __shared__ uint32_t Pw[8][16][36];     // per-warp P  tf32

    const int bh = blockIdx.y;
    const int b = bh >> 4;
    const int h = bh & 15;
    const int tid  = threadIdx.x;
    const int warp = tid >> 5;
    const int lane = tid & 31;
    const int lr = lane >> 2;              // 0..7 (row group)
    const int lc = lane & 3;               // 0..3 (col group)
    const int s0 = blockIdx.x * 128 + warp * 16;

    const int L = memlen[b];
    const int P = pad[b];
    const int Teff = L + P;

    // Q A-fragments (rows s0+lr, s0+lr+8; 8 k-steps over HC=64)
    uint32_t aq[8][4];
    {
        const float* qlo = Q + ((size_t)(s0 + lr) * BATCH + b) * CDIM + h * HC;
        const float* qhi = qlo + (size_t)8 * BATCH * CDIM;
#pragma unroll
        for (int kf = 0; kf < 8; kf++) {
            aq[kf][0] = f2tf32(qlo[kf * 8 + lc]);
            aq[kf][1] = f2tf32(qhi[kf * 8 + lc]);
            aq[kf][2] = f2tf32(qlo[kf * 8 + lc + 4]);
            aq[kf][3] = f2tf32(qhi[kf * 8 + lc + 4]);
        }
    }

    float O[8][4];                         // 8 out-col blocks of 8
#pragma unroll
    for (int nf = 0; nf < 8; nf++)
#pragma unroll
        for (int e = 0; e < 4; e++) O[nf][e] = 0.f;

    float m_lo = NEG_INF, m_hi = NEG_INF, l_lo = 0.f, l_hi = 0.f;

    for (int t0 = 0; t0 < Teff; t0 += KT) {
        __syncthreads();   // previous iteration finished reading Ks/Vs
        // Stage K/V tile (32 keys x 64 floats each): 512 float4 items, 2/thread
#pragma unroll
        for (int i = 0; i < 2; i++) {
            int idx = tid + i * 256;
            int j   = idx >> 4;
            int c4  = (idx & 15) << 2;
            int t   = t0 + j;
            float4 kv = make_float4(0.f, 0.f, 0.f, 0.f);
            float4 vv = make_float4(0.f, 0.f, 0.f, 0.f);
            if (t < L) {
                const float* p = memkv + (((size_t)t * BATCH + b) * HEADS + h) * (2 * HC);
                kv = *(const float4*)(p + c4);
                vv = *(const float4*)(p + HC + c4);
            } else if (t < Teff) {
                size_t base = ((size_t)(t - L) * BATCH + b) * CDIM + h * HC + c4;
                kv = *(const float4*)(Kb + base);
                vv = *(const float4*)(Vb + base);
            }
            Ks[j][c4 + 0] = f2tf32(kv.x); Ks[j][c4 + 1] = f2tf32(kv.y);
            Ks[j][c4 + 2] = f2tf32(kv.z); Ks[j][c4 + 3] = f2tf32(kv.w);
            Vs[j][c4 + 0] = f2tf32(vv.x); Vs[j][c4 + 1] = f2tf32(vv.y);
            Vs[j][c4 + 2] = f2tf32(vv.z); Vs[j][c4 + 3] = f2tf32(vv.w);
        }
        __syncthreads();

        // ---- S = Q K^T : 4 key-blocks of 8 x 8 k-steps ----
        float sc[4][4];
#pragma unroll
        for (int nf = 0; nf < 4; nf++) {
#pragma unroll
            for (int e = 0; e < 4; e++) sc[nf][e] = 0.f;
#pragma unroll
            for (int kk = 0; kk < 8; kk++) {
                uint32_t b0 = Ks[nf * 8 + lr][kk * 8 + lc];
                uint32_t b1 = Ks[nf * 8 + lr][kk * 8 + lc + 4];
                asm volatile(
                    "mma.sync.aligned.m16n8k8.row.col.f32.tf32.tf32.f32 "
                    "{%0,%1,%2,%3}, {%4,%5,%6,%7}, {%8,%9}, {%0,%1,%2,%3};"
                    : "+f"(sc[nf][0]), "+f"(sc[nf][1]),
                      "+f"(sc[nf][2]), "+f"(sc[nf][3])
                    : "r"(aq[kk][0]), "r"(aq[kk][1]),
                      "r"(aq[kk][2]), "r"(aq[kk][3]),
                      "r"(b0), "r"(b1));
            }
        }

        // ---- scale + mask; row max ----
        const bool need_mask = (t0 + KT > L);
        float mx_lo = NEG_INF, mx_hi = NEG_INF;
#pragma unroll
        for (int nf = 0; nf < 4; nf++) {
#pragma unroll
            for (int e = 0; e < 4; e++) {
                int t = t0 + nf * 8 + 2 * lc + (e & 1);
                float v = sc[nf][e] * 0.125f;   // 1/sqrt(HC)
                if (need_mask) {
                    bool valid = (t < Teff);
                    if (valid && t >= L) {
                        int srow = s0 + lr + ((e >= 2) ? 8 : 0);
                        if (mask[((size_t)srow * QS + (t - L)) * BATCH + b]) valid = false;
                    }
                    v = valid ? v : NEG_INF;
                }
                sc[nf][e] = v;
                if (e < 2) mx_lo = fmaxf(mx_lo, v);
                else       mx_hi = fmaxf(mx_hi, v);
            }
        }
        mx_lo = fmaxf(mx_lo, __shfl_xor_sync(0xffffffffu, mx_lo, 1));
        mx_lo = fmaxf(mx_lo, __shfl_xor_sync(0xffffffffu, mx_lo, 2));
        mx_hi = fmaxf(mx_hi, __shfl_xor_sync(0xffffffffu, mx_hi, 1));
        mx_hi = fmaxf(mx_hi, __shfl_xor_sync(0xffffffffu, mx_hi, 2));

        const float mn_lo = fmaxf(m_lo, mx_lo);
        const float mn_hi = fmaxf(m_hi, mx_hi);
        const float corr_lo = (mn_lo > NEG_INF) ? __expf(m_lo - mn_lo) : 1.f;
        const float corr_hi = (mn_hi > NEG_INF) ? __expf(m_hi - mn_hi) : 1.f;

        float sum_lo = 0.f, sum_hi = 0.f;
#pragma unroll
        for (int nf = 0; nf < 4; nf++) {
            float p0 = (mn_lo > NEG_INF) ? __expf(sc[nf][0] - mn_lo) : 0.f;
            float p1 = (mn_lo > NEG_INF) ? __expf(sc[nf][1] - mn_lo) : 0.f;
            float p2 = (mn_hi > NEG_INF) ? __expf(sc[nf][2] - mn_hi) : 0.f;
            float p3 = (mn_hi > NEG_INF) ? __expf(sc[nf][3] - mn_hi) : 0.f;
            sum_lo += p0 + p1;
            sum_hi += p2 + p3;
            sc[nf][0] = p0; sc[nf][1] = p1; sc[nf][2] = p2; sc[nf][3] = p3;
        }
        sum_lo += __shfl_xor_sync(0xffffffffu, sum_lo, 1);
        sum_lo += __shfl_xor_sync(0xffffffffu, sum_lo, 2);
        sum_hi += __shfl_xor_sync(0xffffffffu, sum_hi, 1);
        sum_hi += __shfl_xor_sync(0xffffffffu, sum_hi, 2);

        l_lo = l_lo * corr_lo + sum_lo;
        l_hi = l_hi * corr_hi + sum_hi;
        m_lo = mn_lo; m_hi = mn_hi;

#pragma unroll
        for (int nf = 0; nf < 8; nf++) {
            O[nf][0] *= corr_lo; O[nf][1] *= corr_lo;
            O[nf][2] *= corr_hi; O[nf][3] *= corr_hi;
        }

        // ---- P (C-frag) -> smem (tf32) -> A-frag ----
#pragma unroll
        for (int nf = 0; nf < 4; nf++) {
            Pw[warp][lr][nf * 8 + 2 * lc]         = f2tf32(sc[nf][0]);
            Pw[warp][lr][nf * 8 + 2 * lc + 1]     = f2tf32(sc[nf][1]);
            Pw[warp][lr + 8][nf * 8 + 2 * lc]     = f2tf32(sc[nf][2]);
            Pw[warp][lr + 8][nf * 8 + 2 * lc + 1] = f2tf32(sc[nf][3]);
        }
        __syncwarp();
        uint32_t ap[4][4];
#pragma unroll
        for (int kk = 0; kk < 4; kk++) {
            ap[kk][0] = Pw[warp][lr][kk * 8 + lc];
            ap[kk][1] = Pw[warp][lr + 8][kk * 8 + lc];
            ap[kk][2] = Pw[warp][lr][kk * 8 + lc + 4];
            ap[kk][3] = Pw[warp][lr + 8][kk * 8 + lc + 4];
        }
        __syncwarp();

        // ---- O += P V : 8 out-col blocks x 4 key-chunks ----
#pragma unroll
        for (int nf = 0; nf < 8; nf++) {
#pragma unroll
            for (int kk = 0; kk < 4; kk++) {
                uint32_t b0 = Vs[kk * 8 + lc][nf * 8 + lr];
                uint32_t b1 = Vs[kk * 8 + lc + 4][nf * 8 + lr];
                asm volatile(
                    "mma.sync.aligned.m16n8k8.row.col.f32.tf32.tf32.f32 "
                    "{%0,%1,%2,%3}, {%4,%5,%6,%7}, {%8,%9}, {%0,%1,%2,%3};"
                    : "+f"(O[nf][0]), "+f"(O[nf][1]),
                      "+f"(O[nf][2]), "+f"(O[nf][3])
                    : "r"(ap[kk][0]), "r"(ap[kk][1]),
                      "r"(ap[kk][2]), "r"(ap[kk][3]),
                      "r"(b0), "r"(b1));
            }
        }
    }

    // Epilogue: normalize (nan_to_num -> 0 for empty rows) and store.
    const float inv_lo = (l_lo > 0.f) ? (1.f / l_lo) : 0.f;
    const float inv_hi = (l_hi > 0.f) ? (1.f / l_hi) : 0.f;
    float* xlo = X + ((size_t)(s0 + lr) * BATCH + b) * CDIM + h * HC;
    float* xhi = xlo + (size_t)8 * BATCH * CDIM;
#pragma unroll
    for (int nf = 0; nf < 8; nf++) {
        int c = nf * 8 + 2 * lc;
        *(float2*)(xlo + c) = make_float2(O[nf][0] * inv_lo, O[nf][1] * inv_lo);
        *(float2*)(xhi + c) = make_float2(O[nf][2] * inv_hi, O[nf][3] * inv_hi);
    }
}

// ---------------------------------------------------------------------------
// Launch: QKV GEMM (tf32) -> attention (tf32 MMA) -> output GEMM (tf32).
// Input order: xq, pad, mask, memory_length, memory_kv,
//              Wq, bq, Wk, bk, Wv, bv, Wo, bo
// ---------------------------------------------------------------------------
extern "C" void kernel_launch(void* const* d_in, const int* in_sizes, int n_in,
                              void* d_out, int out_size)
{
    const float*         xq     = (const float*)d_in[0];
    const int*           padv   = (const int*)d_in[1];
    const unsigned char* mask   = (const unsigned char*)d_in[2];
    const int*           memlen = (const int*)d_in[3];
    const float*         memkv  = (const float*)d_in[4];
    const float*         Wq     = (const float*)d_in[5];
    const float*         bq     = (const float*)d_in[6];
    const float*         Wk     = (const float*)d_in[7];
    const float*         bk     = (const float*)d_in[8];
    const float*         Wv     = (const float*)d_in[9];
    const float*         bv     = (const float*)d_in[10];
    const float*         Wo     = (const float*)d_in[11];
    const float*         bo     = (const float*)d_in[12];
    float*               out    = (float*)d_out;

    float *qb, *kb, *vb, *xb;
    cudaGetSymbolAddress((void**)&qb, g_qbuf);
    cudaGetSymbolAddress((void**)&kb, g_kbuf);
    cudaGetSymbolAddress((void**)&vb, g_vbuf);
    cudaGetSymbolAddress((void**)&xb, g_xbuf);

    GemmSet sq{Wq, bq, qb};
    GemmSet sk{Wk, bk, kb};
    GemmSet sv{Wv, bv, vb};
    GemmSet so{Wo, bo, out};

    // Fused QKV projection: M=4096, N=3*1024, K=1024
    gemm_tf32_multi<<<dim3(32, 24), 256>>>(xq, sq, sk, sv);

    // Attention: 4 q-tiles x (B*H=128), tensor-core
    attn_mma<<<dim3(4, 128), 256>>>(qb, kb, vb, memkv, memlen, padv, mask, xb);

    // Output projection: M=4096, N=1024, K=1024
    gemm_tf32_multi<<<dim3(32, 8), 256>>>(xb, so, so, so);
}

// round 16
// speedup vs baseline: 2.9801x; 1.0532x over previous
#include <cuda_runtime.h>
#include <cstdint>

// Problem constants
#define QS    512
#define BATCH 8
#define CDIM  1024
#define HEADS 16
#define HC    64
#define MMEM  1536

#define NEG_INF (__int_as_float(0xff800000))

// Scratch (device globals — no allocation allowed)
__device__ float g_qbuf[QS * BATCH * CDIM];
__device__ float g_kbuf[QS * BATCH * CDIM];
__device__ float g_vbuf[QS * BATCH * CDIM];
__device__ float g_xbuf[QS * BATCH * CDIM];
__device__ float g_xqt [QS * BATCH * CDIM];     // tf32-rounded xq
__device__ float g_wt  [4][CDIM * CDIM];        // tf32-rounded Wq,Wk,Wv,Wo

struct GemmSet { const float* W; const float* bias; float* out; };

__device__ __forceinline__ uint32_t f2tf32(float x) {
    uint32_t u;
    asm("cvt.rna.tf32.f32 %0, %1;" : "=r"(u) : "f"(x));
    return u;
}

__device__ __forceinline__ void cp_async16(void* smem, const void* gmem) {
    uint32_t s = (uint32_t)__cvta_generic_to_shared(smem);
    asm volatile("cp.async.cg.shared.global [%0], [%1], 16;" :: "r"(s), "l"(gmem));
}

// ---------------------------------------------------------------------------
// Pre-round fp32 -> tf32(rna) elementwise. grid.y selects segment.
// ---------------------------------------------------------------------------
__global__ __launch_bounds__(256) void round_tf32_multi(
    const float* __restrict__ xq,
    const float* __restrict__ wq, const float* __restrict__ wk,
    const float* __restrict__ wv, const float* __restrict__ wo,
    float* __restrict__ xqt, float* __restrict__ wt)
{
    const float* in; float* out; int n4;
    switch (blockIdx.y) {
        case 0: in = xq; out = xqt;                  n4 = QS * BATCH * CDIM / 4; break;
        case 1: in = wq; out = wt;                   n4 = CDIM * CDIM / 4;       break;
        case 2: in = wk; out = wt + CDIM * CDIM;     n4 = CDIM * CDIM / 4;       break;
        case 3: in = wv; out = wt + 2 * CDIM * CDIM; n4 = CDIM * CDIM / 4;       break;
        default:in = wo; out = wt + 3 * CDIM * CDIM; n4 = CDIM * CDIM / 4;       break;
    }
    for (int i = blockIdx.x * blockDim.x + threadIdx.x; i < n4;
         i += gridDim.x * blockDim.x) {
        float4 v = ((const float4*)in)[i];
        uint4 u = make_uint4(f2tf32(v.x), f2tf32(v.y), f2tf32(v.z), f2tf32(v.w));
        ((uint4*)out)[i] = u;
    }
}

// ---------------------------------------------------------------------------
// TF32 tensor-core GEMM, 2-stage cp.async pipeline.
// out[m,n] = sum_k A[m,k]*W[n,k] + bias[n]; A and W PRE-ROUNDED to tf32.
// Tile 128x128x32, 256 threads, warp tile 64x32 (m16n8k8). Dynamic smem:
// As[2][128][36] + Bs[2][128][36] = 73728 B.
// ---------------------------------------------------------------------------
__global__ __launch_bounds__(256, 2) void gemm_tf32_pipe(
    const float* __restrict__ A, GemmSet s0, GemmSet s1, GemmSet s2)
{
    constexpr int K = 1024, BK = 32, NIT = K / BK;
    extern __shared__ uint32_t dsm[];
    uint32_t (*As)[36] = (uint32_t(*)[36])dsm;                    // [2*128][36]
    uint32_t (*Bs)[36] = (uint32_t(*)[36])(dsm + 2 * 128 * 36);   // [2*128][36]

    const int mat = blockIdx.y >> 3;
    const int bn  = blockIdx.y & 7;
    GemmSet g = (mat == 0) ? s0 : (mat == 1) ? s1 : s2;

    const int m0 = blockIdx.x * 128;
    const int n0 = bn * 128;
    const int tid  = threadIdx.x;
    const int warp = tid >> 5;
    const int lane = tid & 31;
    const int wm = (warp >> 2) * 64;
    const int wn = (warp & 3) * 32;
    const int lr = lane >> 2;
    const int lc = lane & 3;

    const float* Ag = A   + (size_t)m0 * K;
    const float* Wg = g.W + (size_t)n0 * K;

    const int srow = tid >> 3;             // staging row base (0..31)
    const int skq  = (tid & 7) << 2;       // staging k-offset (0,4,...,28)

#define STAGE(it, buf)                                                        \
    do {                                                                      \
        int _k0 = (it) * BK;                                                  \
        _Pragma("unroll")                                                     \
        for (int _i = 0; _i < 4; _i++) {                                      \
            int _row = srow + _i * 32;                                        \
            cp_async16(&As[(buf) * 128 + _row][skq],                          \
                       Ag + (size_t)_row * K + _k0 + skq);                    \
            cp_async16(&Bs[(buf) * 128 + _row][skq],                          \
                       Wg + (size_t)_row * K + _k0 + skq);                    \
        }                                                                     \
        asm volatile("cp.async.commit_group;" ::: "memory");                  \
    } while (0)

    float acc[4][4][4];
#pragma unroll
    for (int mi = 0; mi < 4; mi++)
#pragma unroll
        for (int ni = 0; ni < 4; ni++)
#pragma unroll
            for (int c = 0; c < 4; c++) acc[mi][ni][c] = 0.f;

    STAGE(0, 0);

    for (int it = 0; it < NIT; it++) {
        const int buf = it & 1;
        if (it + 1 < NIT) {
            STAGE(it + 1, buf ^ 1);
            asm volatile("cp.async.wait_group 1;" ::: "memory");
        } else {
            asm volatile("cp.async.wait_group 0;" ::: "memory");
        }
        __syncthreads();

        const uint32_t (*Ab)[36] = As + buf * 128;
        const uint32_t (*Bb)[36] = Bs + buf * 128;
#pragma unroll
        for (int kk = 0; kk < BK; kk += 8) {
            uint32_t af[4][4], bf[4][2];
#pragma unroll
            for (int mi = 0; mi < 4; mi++) {
                int r = wm + mi * 16 + lr;
                af[mi][0] = Ab[r][kk + lc];
                af[mi][1] = Ab[r + 8][kk + lc];
                af[mi][2] = Ab[r][kk + lc + 4];
                af[mi][3] = Ab[r + 8][kk + lc + 4];
            }
#pragma unroll
            for (int ni = 0; ni < 4; ni++) {
                int n = wn + ni * 8 + lr;
                bf[ni][0] = Bb[n][kk + lc];
                bf[ni][1] = Bb[n][kk + lc + 4];
            }
#pragma unroll
            for (int mi = 0; mi < 4; mi++)
#pragma unroll
                for (int ni = 0; ni < 4; ni++) {
                    asm volatile(
                        "mma.sync.aligned.m16n8k8.row.col.f32.tf32.tf32.f32 "
                        "{%0,%1,%2,%3}, {%4,%5,%6,%7}, {%8,%9}, {%0,%1,%2,%3};"
                        : "+f"(acc[mi][ni][0]), "+f"(acc[mi][ni][1]),
                          "+f"(acc[mi][ni][2]), "+f"(acc[mi][ni][3])
                        : "r"(af[mi][0]), "r"(af[mi][1]),
                          "r"(af[mi][2]), "r"(af[mi][3]),
                          "r"(bf[ni][0]), "r"(bf[ni][1]));
                }
        }
        __syncthreads();
    }
#undef STAGE

#pragma unroll
    for (int ni = 0; ni < 4; ni++) {
        int c = n0 + wn + ni * 8 + 2 * lc;
        float bias0 = g.bias[c];
        float bias1 = g.bias[c + 1];
#pragma unroll
        for (int mi = 0; mi < 4; mi++) {
            int r = m0 + wm + mi * 16 + lr;
            float2 v0 = make_float2(acc[mi][ni][0] + bias0, acc[mi][ni][1] + bias1);
            float2 v1 = make_float2(acc[mi][ni][2] + bias0, acc[mi][ni][3] + bias1);
            *(float2*)(g.out + (size_t)r * 1024 + c)       = v0;
            *(float2*)(g.out + (size_t)(r + 8) * 1024 + c) = v1;
        }
    }
}

// ---------------------------------------------------------------------------
// Tensor-core flash attention (validated at 286us in round 13; epilogue
// stores tf32-rounded values so the O-proj GEMM streams pre-rounded input).
// ---------------------------------------------------------------------------
__global__ __launch_bounds__(256, 2) void attn_mma(
    const float* __restrict__ Q, const float* __restrict__ Kb,
    const float* __restrict__ Vb, const float* __restrict__ memkv,
    const int* __restrict__ memlen, const int* __restrict__ pad,
    const unsigned char* __restrict__ mask, float* __restrict__ X)
{
    constexpr int KT = 32;
    __shared__ uint32_t Ks[KT][68];
    __shared__ uint32_t Vs[KT][72];
    __shared__ uint32_t Pw[8][16][36];

    const int bh = blockIdx.y;
    const int b = bh >> 4;
    const int h = bh & 15;
    const int tid  = threadIdx.x;
    const int warp = tid >> 5;
    const int lane = tid & 31;
    const int lr = lane >> 2;
    const int lc = lane & 3;
    const int s0 = blockIdx.x * 128 + warp * 16;

    const int L = memlen[b];
    const int P = pad[b];
    const int Teff = L + P;

    uint32_t aq[8][4];
    {
        const float* qlo = Q + ((size_t)(s0 + lr) * BATCH + b) * CDIM + h * HC;
        const float* qhi = qlo + (size_t)8 * BATCH * CDIM;
#pragma unroll
        for (int kf = 0; kf < 8; kf++) {
            aq[kf][0] = f2tf32(qlo[kf * 8 + lc]);
            aq[kf][1] = f2tf32(qhi[kf * 8 + lc]);
            aq[kf][2] = f2tf32(qlo[kf * 8 + lc + 4]);
            aq[kf][3] = f2tf32(qhi[kf * 8 + lc + 4]);
        }
    }

    float O[8][4];
#pragma unroll
    for (int nf = 0; nf < 8; nf++)
#pragma unroll
        for (int e = 0; e < 4; e++) O[nf][e] = 0.f;

    float m_lo = NEG_INF, m_hi = NEG_INF, l_lo = 0.f, l_hi = 0.f;

    for (int t0 = 0; t0 < Teff; t0 += KT) {
        __syncthreads();
#pragma unroll
        for (int i = 0; i < 2; i++) {
            int idx = tid + i * 256;
            int j   = idx >> 4;
            int c4  = (idx & 15) << 2;
            int t   = t0 + j;
            float4 kv = make_float4(0.f, 0.f, 0.f, 0.f);
            float4 vv = make_float4(0.f, 0.f, 0.f, 0.f);
            if (t < L) {
                const float* p = memkv + (((size_t)t * BATCH + b) * HEADS + h) * (2 * HC);
                kv = *(const float4*)(p + c4);
                vv = *(const float4*)(p + HC + c4);
            } else if (t < Teff) {
                size_t base = ((size_t)(t - L) * BATCH + b) * CDIM + h * HC + c4;
                kv = *(const float4*)(Kb + base);
                vv = *(const float4*)(Vb + base);
            }
            Ks[j][c4 + 0] = f2tf32(kv.x); Ks[j][c4 + 1] = f2tf32(kv.y);
            Ks[j][c4 + 2] = f2tf32(kv.z); Ks[j][c4 + 3] = f2tf32(kv.w);
            Vs[j][c4 + 0] = f2tf32(vv.x); Vs[j][c4 + 1] = f2tf32(vv.y);
            Vs[j][c4 + 2] = f2tf32(vv.z); Vs[j][c4 + 3] = f2tf32(vv.w);
        }
        __syncthreads();

        float sc[4][4];
#pragma unroll
        for (int nf = 0; nf < 4; nf++) {
#pragma unroll
            for (int e = 0; e < 4; e++) sc[nf][e] = 0.f;
#pragma unroll
            for (int kk = 0; kk < 8; kk++) {
                uint32_t b0 = Ks[nf * 8 + lr][kk * 8 + lc];
                uint32_t b1 = Ks[nf * 8 + lr][kk * 8 + lc + 4];
                asm volatile(
                    "mma.sync.aligned.m16n8k8.row.col.f32.tf32.tf32.f32 "
                    "{%0,%1,%2,%3}, {%4,%5,%6,%7}, {%8,%9}, {%0,%1,%2,%3};"
                    : "+f"(sc[nf][0]), "+f"(sc[nf][1]),
                      "+f"(sc[nf][2]), "+f"(sc[nf][3])
                    : "r"(aq[kk][0]), "r"(aq[kk][1]),
                      "r"(aq[kk][2]), "r"(aq[kk][3]),
                      "r"(b0), "r"(b1));
            }
        }

        const bool need_mask = (t0 + KT > L);
        float mx_lo = NEG_INF, mx_hi = NEG_INF;
#pragma unroll
        for (int nf = 0; nf < 4; nf++) {
#pragma unroll
            for (int e = 0; e < 4; e++) {
                int t = t0 + nf * 8 + 2 * lc + (e & 1);
                float v = sc[nf][e] * 0.125f;
                if (need_mask) {
                    bool valid = (t < Teff);
                    if (valid && t >= L) {
                        int srow = s0 + lr + ((e >= 2) ? 8 : 0);
                        if (mask[((size_t)srow * QS + (t - L)) * BATCH + b]) valid = false;
                    }
                    v = valid ? v : NEG_INF;
                }
                sc[nf][e] = v;
                if (e < 2) mx_lo = fmaxf(mx_lo, v);
                else       mx_hi = fmaxf(mx_hi, v);
            }
        }
        mx_lo = fmaxf(mx_lo, __shfl_xor_sync(0xffffffffu, mx_lo, 1));
        mx_lo = fmaxf(mx_lo, __shfl_xor_sync(0xffffffffu, mx_lo, 2));
        mx_hi = fmaxf(mx_hi, __shfl_xor_sync(0xffffffffu, mx_hi, 1));
        mx_hi = fmaxf(mx_hi, __shfl_xor_sync(0xffffffffu, mx_hi, 2));

        const float mn_lo = fmaxf(m_lo, mx_lo);
        const float mn_hi = fmaxf(m_hi, mx_hi);
        const float corr_lo = (mn_lo > NEG_INF) ? __expf(m_lo - mn_lo) : 1.f;
        const float corr_hi = (mn_hi > NEG_INF) ? __expf(m_hi - mn_hi) : 1.f;

        float sum_lo = 0.f, sum_hi = 0.f;
#pragma unroll
        for (int nf = 0; nf < 4; nf++) {
            float p0 = (mn_lo > NEG_INF) ? __expf(sc[nf][0] - mn_lo) : 0.f;
            float p1 = (mn_lo > NEG_INF) ? __expf(sc[nf][1] - mn_lo) : 0.f;
            float p2 = (mn_hi > NEG_INF) ? __expf(sc[nf][2] - mn_hi) : 0.f;
            float p3 = (mn_hi > NEG_INF) ? __expf(sc[nf][3] - mn_hi) : 0.f;
            sum_lo += p0 + p1;
            sum_hi += p2 + p3;
            sc[nf][0] = p0; sc[nf][1] = p1; sc[nf][2] = p2; sc[nf][3] = p3;
        }
        sum_lo += __shfl_xor_sync(0xffffffffu, sum_lo, 1);
        sum_lo += __shfl_xor_sync(0xffffffffu, sum_lo, 2);
        sum_hi += __shfl_xor_sync(0xffffffffu, sum_hi, 1);
        sum_hi += __shfl_xor_sync(0xffffffffu, sum_hi, 2);

        l_lo = l_lo * corr_lo + sum_lo;
        l_hi = l_hi * corr_hi + sum_hi;
        m_lo = mn_lo; m_hi = mn_hi;

#pragma unroll
        for (int nf = 0; nf < 8; nf++) {
            O[nf][0] *= corr_lo; O[nf][1] *= corr_lo;
            O[nf][2] *= corr_hi; O[nf][3] *= corr_hi;
        }

#pragma unroll
        for (int nf = 0; nf < 4; nf++) {
            Pw[warp][lr][nf * 8 + 2 * lc]         = f2tf32(sc[nf][0]);
            Pw[warp][lr][nf * 8 + 2 * lc + 1]     = f2tf32(sc[nf][1]);
            Pw[warp][lr + 8][nf * 8 + 2 * lc]     = f2tf32(sc[nf][2]);
            Pw[warp][lr + 8][nf * 8 + 2 * lc + 1] = f2tf32(sc[nf][3]);
        }
        __syncwarp();
        uint32_t ap[4][4];
#pragma unroll
        for (int kk = 0; kk < 4; kk++) {
            ap[kk][0] = Pw[warp][lr][kk * 8 + lc];
            ap[kk][1] = Pw[warp][lr + 8][kk * 8 + lc];
            ap[kk][2] = Pw[warp][lr][kk * 8 + lc + 4];
            ap[kk][3] = Pw[warp][lr + 8][kk * 8 + lc + 4];
        }
        __syncwarp();

#pragma unroll
        for (int nf = 0; nf < 8; nf++) {
#pragma unroll
            for (int kk = 0; kk < 4; kk++) {
                uint32_t b0 = Vs[kk * 8 + lc][nf * 8 + lr];
                uint32_t b1 = Vs[kk * 8 + lc + 4][nf * 8 + lr];
                asm volatile(
                    "mma.sync.aligned.m16n8k8.row.col.f32.tf32.tf32.f32 "
                    "{%0,%1,%2,%3}, {%4,%5,%6,%7}, {%8,%9}, {%0,%1,%2,%3};"
                    : "+f"(O[nf][0]), "+f"(O[nf][1]),
                      "+f"(O[nf][2]), "+f"(O[nf][3])
                    : "r"(ap[kk][0]), "r"(ap[kk][1]),
                      "r"(ap[kk][2]), "r"(ap[kk][3]),
                      "r"(b0), "r"(b1));
            }
        }
    }

    // Epilogue: normalize, round to tf32 (feeds O-proj GEMM directly), store.
    const float inv_lo = (l_lo > 0.f) ? (1.f / l_lo) : 0.f;
    const float inv_hi = (l_hi > 0.f) ? (1.f / l_hi) : 0.f;
    float* xlo = X + ((size_t)(s0 + lr) * BATCH + b) * CDIM + h * HC;
    float* xhi = xlo + (size_t)8 * BATCH * CDIM;
#pragma unroll
    for (int nf = 0; nf < 8; nf++) {
        int c = nf * 8 + 2 * lc;
        *(float2*)(xlo + c) = make_float2(
            __uint_as_float(f2tf32(O[nf][0] * inv_lo)),
            __uint_as_float(f2tf32(O[nf][1] * inv_lo)));
        *(float2*)(xhi + c) = make_float2(
            __uint_as_float(f2tf32(O[nf][2] * inv_hi)),
            __uint_as_float(f2tf32(O[nf][3] * inv_hi)));
    }
}

// ---------------------------------------------------------------------------
// Launch: pre-round -> QKV GEMM (pipelined) -> attention -> O GEMM.
// Input order: xq, pad, mask, memory_length, memory_kv,
//              Wq, bq, Wk, bk, Wv, bv, Wo, bo
// ---------------------------------------------------------------------------
extern "C" void kernel_launch(void* const* d_in, const int* in_sizes, int n_in,
                              void* d_out, int out_size)
{
    const float*         xq     = (const float*)d_in[0];
    const int*           padv   = (const int*)d_in[1];
    const unsigned char* mask   = (const unsigned char*)d_in[2];
    const int*           memlen = (const int*)d_in[3];
    const float*         memkv  = (const float*)d_in[4];
    const float*         Wq     = (const float*)d_in[5];
    const float*         bq     = (const float*)d_in[6];
    const float*         Wk     = (const float*)d_in[7];
    const float*         bk     = (const float*)d_in[8];
    const float*         Wv     = (const float*)d_in[9];
    const float*         bv     = (const float*)d_in[10];
    const float*         Wo     = (const float*)d_in[11];
    const float*         bo     = (const float*)d_in[12];
    float*               out    = (float*)d_out;

    float *qb, *kb, *vb, *xb, *xqt, *wt;
    cudaGetSymbolAddress((void**)&qb,  g_qbuf);
    cudaGetSymbolAddress((void**)&kb,  g_kbuf);
    cudaGetSymbolAddress((void**)&vb,  g_vbuf);
    cudaGetSymbolAddress((void**)&xb,  g_xbuf);
    cudaGetSymbolAddress((void**)&xqt, g_xqt);
    cudaGetSymbolAddress((void**)&wt,  g_wt);

    const int GEMM_SMEM = 2 * 2 * 128 * 36 * 4;   // 73728 B
    (void)cudaFuncSetAttribute(gemm_tf32_pipe,
                               cudaFuncAttributeMaxDynamicSharedMemorySize,
                               GEMM_SMEM);

    // Pre-round xq and weights to tf32 (rna)
    round_tf32_multi<<<dim3(1024, 5), 256>>>(xq, Wq, Wk, Wv, Wo, xqt, wt);

    GemmSet sq{wt,                 bq, qb};
    GemmSet sk{wt + CDIM * CDIM,   bk, kb};
    GemmSet sv{wt + 2*CDIM*CDIM,   bv, vb};
    GemmSet so{wt + 3*CDIM*CDIM,   bo, out};

    // Fused QKV projection: M=4096, N=3*1024, K=1024
    gemm_tf32_pipe<<<dim3(32, 24), 256, GEMM_SMEM>>>(xqt, sq, sk, sv);

    // Attention: 4 q-tiles x (B*H=128)
    attn_mma<<<dim3(4, 128), 256>>>(qb, kb, vb, memkv, memlen, padv, mask, xb);

    // Output projection: M=4096, N=1024, K=1024
    gemm_tf32_pipe<<<dim3(32, 8), 256, GEMM_SMEM>>>(xb, so, so, so);
}

// round 17
// speedup vs baseline: 3.2441x; 1.0886x over previous
#include <cuda_runtime.h>
#include <cstdint>

// Problem constants
#define QS    512
#define BATCH 8
#define CDIM  1024
#define HEADS 16
#define HC    64
#define MMEM  1536

#define NEG_INF (__int_as_float(0xff800000))

// Scratch (device globals — no allocation allowed)
__device__ float g_qbuf[QS * BATCH * CDIM];
__device__ float g_kbuf[QS * BATCH * CDIM];
__device__ float g_vbuf[QS * BATCH * CDIM];
__device__ float g_xbuf[QS * BATCH * CDIM];
__device__ float g_xqt [QS * BATCH * CDIM];     // tf32-rounded xq
__device__ float g_wt  [4][CDIM * CDIM];        // tf32-rounded Wq,Wk,Wv,Wo

struct GemmSet { const float* W; const float* bias; float* out; };

__device__ __forceinline__ uint32_t f2tf32(float x) {
    uint32_t u;
    asm("cvt.rna.tf32.f32 %0, %1;" : "=r"(u) : "f"(x));
    return u;
}

__device__ __forceinline__ void cp_async16(void* smem, const void* gmem) {
    uint32_t s = (uint32_t)__cvta_generic_to_shared(smem);
    asm volatile("cp.async.cg.shared.global [%0], [%1], 16;" :: "r"(s), "l"(gmem));
}

// ---------------------------------------------------------------------------
// Pre-round fp32 -> tf32(rna) elementwise. grid.y selects segment.
// ---------------------------------------------------------------------------
__global__ __launch_bounds__(256) void round_tf32_multi(
    const float* __restrict__ xq,
    const float* __restrict__ wq, const float* __restrict__ wk,
    const float* __restrict__ wv, const float* __restrict__ wo,
    float* __restrict__ xqt, float* __restrict__ wt)
{
    const float* in; float* out; int n4;
    switch (blockIdx.y) {
        case 0: in = xq; out = xqt;                  n4 = QS * BATCH * CDIM / 4; break;
        case 1: in = wq; out = wt;                   n4 = CDIM * CDIM / 4;       break;
        case 2: in = wk; out = wt + CDIM * CDIM;     n4 = CDIM * CDIM / 4;       break;
        case 3: in = wv; out = wt + 2 * CDIM * CDIM; n4 = CDIM * CDIM / 4;       break;
        default:in = wo; out = wt + 3 * CDIM * CDIM; n4 = CDIM * CDIM / 4;       break;
    }
    for (int i = blockIdx.x * blockDim.x + threadIdx.x; i < n4;
         i += gridDim.x * blockDim.x) {
        float4 v = ((const float4*)in)[i];
        uint4 u = make_uint4(f2tf32(v.x), f2tf32(v.y), f2tf32(v.z), f2tf32(v.w));
        ((uint4*)out)[i] = u;
    }
}

// ---------------------------------------------------------------------------
// TF32 tensor-core GEMM, 2-stage cp.async pipeline (unchanged from round 16).
// ---------------------------------------------------------------------------
__global__ __launch_bounds__(256, 2) void gemm_tf32_pipe(
    const float* __restrict__ A, GemmSet s0, GemmSet s1, GemmSet s2)
{
    constexpr int K = 1024, BK = 32, NIT = K / BK;
    extern __shared__ uint32_t dsm[];
    uint32_t (*As)[36] = (uint32_t(*)[36])dsm;                    // [2*128][36]
    uint32_t (*Bs)[36] = (uint32_t(*)[36])(dsm + 2 * 128 * 36);   // [2*128][36]

    const int mat = blockIdx.y >> 3;
    const int bn  = blockIdx.y & 7;
    GemmSet g = (mat == 0) ? s0 : (mat == 1) ? s1 : s2;

    const int m0 = blockIdx.x * 128;
    const int n0 = bn * 128;
    const int tid  = threadIdx.x;
    const int warp = tid >> 5;
    const int lane = tid & 31;
    const int wm = (warp >> 2) * 64;
    const int wn = (warp & 3) * 32;
    const int lr = lane >> 2;
    const int lc = lane & 3;

    const float* Ag = A   + (size_t)m0 * K;
    const float* Wg = g.W + (size_t)n0 * K;

    const int srow = tid >> 3;
    const int skq  = (tid & 7) << 2;

#define STAGE(it, buf)                                                        \
    do {                                                                      \
        int _k0 = (it) * BK;                                                  \
        _Pragma("unroll")                                                     \
        for (int _i = 0; _i < 4; _i++) {                                      \
            int _row = srow + _i * 32;                                        \
            cp_async16(&As[(buf) * 128 + _row][skq],                          \
                       Ag + (size_t)_row * K + _k0 + skq);                    \
            cp_async16(&Bs[(buf) * 128 + _row][skq],                          \
                       Wg + (size_t)_row * K + _k0 + skq);                    \
        }                                                                     \
        asm volatile("cp.async.commit_group;" ::: "memory");                  \
    } while (0)

    float acc[4][4][4];
#pragma unroll
    for (int mi = 0; mi < 4; mi++)
#pragma unroll
        for (int ni = 0; ni < 4; ni++)
#pragma unroll
            for (int c = 0; c < 4; c++) acc[mi][ni][c] = 0.f;

    STAGE(0, 0);

    for (int it = 0; it < NIT; it++) {
        const int buf = it & 1;
        if (it + 1 < NIT) {
            STAGE(it + 1, buf ^ 1);
            asm volatile("cp.async.wait_group 1;" ::: "memory");
        } else {
            asm volatile("cp.async.wait_group 0;" ::: "memory");
        }
        __syncthreads();

        const uint32_t (*Ab)[36] = As + buf * 128;
        const uint32_t (*Bb)[36] = Bs + buf * 128;
#pragma unroll
        for (int kk = 0; kk < BK; kk += 8) {
            uint32_t af[4][4], bf[4][2];
#pragma unroll
            for (int mi = 0; mi < 4; mi++) {
                int r = wm + mi * 16 + lr;
                af[mi][0] = Ab[r][kk + lc];
                af[mi][1] = Ab[r + 8][kk + lc];
                af[mi][2] = Ab[r][kk + lc + 4];
                af[mi][3] = Ab[r + 8][kk + lc + 4];
            }
#pragma unroll
            for (int ni = 0; ni < 4; ni++) {
                int n = wn + ni * 8 + lr;
                bf[ni][0] = Bb[n][kk + lc];
                bf[ni][1] = Bb[n][kk + lc + 4];
            }
#pragma unroll
            for (int mi = 0; mi < 4; mi++)
#pragma unroll
                for (int ni = 0; ni < 4; ni++) {
                    asm volatile(
                        "mma.sync.aligned.m16n8k8.row.col.f32.tf32.tf32.f32 "
                        "{%0,%1,%2,%3}, {%4,%5,%6,%7}, {%8,%9}, {%0,%1,%2,%3};"
                        : "+f"(acc[mi][ni][0]), "+f"(acc[mi][ni][1]),
                          "+f"(acc[mi][ni][2]), "+f"(acc[mi][ni][3])
                        : "r"(af[mi][0]), "r"(af[mi][1]),
                          "r"(af[mi][2]), "r"(af[mi][3]),
                          "r"(bf[ni][0]), "r"(bf[ni][1]));
                }
        }
        __syncthreads();
    }
#undef STAGE

#pragma unroll
    for (int ni = 0; ni < 4; ni++) {
        int c = n0 + wn + ni * 8 + 2 * lc;
        float bias0 = g.bias[c];
        float bias1 = g.bias[c + 1];
#pragma unroll
        for (int mi = 0; mi < 4; mi++) {
            int r = m0 + wm + mi * 16 + lr;
            float2 v0 = make_float2(acc[mi][ni][0] + bias0, acc[mi][ni][1] + bias1);
            float2 v1 = make_float2(acc[mi][ni][2] + bias0, acc[mi][ni][3] + bias1);
            *(float2*)(g.out + (size_t)r * 1024 + c)       = v0;
            *(float2*)(g.out + (size_t)(r + 8) * 1024 + c) = v1;
        }
    }
}

// ---------------------------------------------------------------------------
// Tensor-core flash attention with register-prefetch double buffering:
// K/V gmem loads for tile t+1 are issued before the compute of tile t,
// hiding global latency behind the MMA/softmax work.
// ---------------------------------------------------------------------------
__global__ __launch_bounds__(256, 2) void attn_mma(
    const float* __restrict__ Q, const float* __restrict__ Kb,
    const float* __restrict__ Vb, const float* __restrict__ memkv,
    const int* __restrict__ memlen, const int* __restrict__ pad,
    const unsigned char* __restrict__ mask, float* __restrict__ X)
{
    constexpr int KT = 32;
    __shared__ uint32_t Ks[KT][68];
    __shared__ uint32_t Vs[KT][72];
    __shared__ uint32_t Pw[8][16][36];

    const int bh = blockIdx.y;
    const int b = bh & 7;                  // batch fastest: mixes Teff per wave
    const int h = bh >> 3;
    const int tid  = threadIdx.x;
    const int warp = tid >> 5;
    const int lane = tid & 31;
    const int lr = lane >> 2;
    const int lc = lane & 3;
    const int s0 = blockIdx.x * 128 + warp * 16;

    const int L = memlen[b];
    const int P = pad[b];
    const int Teff = L + P;

    // Per-thread staging coordinates (2 slots: keys j0 and j0+16)
    const int j0 = tid >> 4;               // 0..15
    const int c4 = (tid & 15) << 2;        // 0,4,...,60

    float4 pk[2], pv[2];
#define PREFETCH(t0n)                                                          \
    do {                                                                       \
        _Pragma("unroll")                                                      \
        for (int _i = 0; _i < 2; _i++) {                                       \
            int _t = (t0n) + j0 + _i * 16;                                     \
            pk[_i] = make_float4(0.f, 0.f, 0.f, 0.f);                          \
            pv[_i] = make_float4(0.f, 0.f, 0.f, 0.f);                          \
            if (_t < L) {                                                      \
                const float* _p = memkv +                                      \
                    (((size_t)_t * BATCH + b) * HEADS + h) * (2 * HC);         \
                pk[_i] = *(const float4*)(_p + c4);                            \
                pv[_i] = *(const float4*)(_p + HC + c4);                       \
            } else if (_t < Teff) {                                            \
                size_t _base = ((size_t)(_t - L) * BATCH + b) * CDIM           \
                               + h * HC + c4;                                  \
                pk[_i] = *(const float4*)(Kb + _base);                         \
                pv[_i] = *(const float4*)(Vb + _base);                         \
            }                                                                  \
        }                                                                      \
    } while (0)

    uint32_t aq[8][4];
    {
        const float* qlo = Q + ((size_t)(s0 + lr) * BATCH + b) * CDIM + h * HC;
        const float* qhi = qlo + (size_t)8 * BATCH * CDIM;
#pragma unroll
        for (int kf = 0; kf < 8; kf++) {
            aq[kf][0] = f2tf32(qlo[kf * 8 + lc]);
            aq[kf][1] = f2tf32(qhi[kf * 8 + lc]);
            aq[kf][2] = f2tf32(qlo[kf * 8 + lc + 4]);
            aq[kf][3] = f2tf32(qhi[kf * 8 + lc + 4]);
        }
    }

    float O[8][4];
#pragma unroll
    for (int nf = 0; nf < 8; nf++)
#pragma unroll
        for (int e = 0; e < 4; e++) O[nf][e] = 0.f;

    float m_lo = NEG_INF, m_hi = NEG_INF, l_lo = 0.f, l_hi = 0.f;

    if (Teff > 0) PREFETCH(0);

    for (int t0 = 0; t0 < Teff; t0 += KT) {
        __syncthreads();   // all warps done reading previous tile
        // Commit prefetched tile t0 to shared (cvt to tf32)
#pragma unroll
        for (int i = 0; i < 2; i++) {
            int j = j0 + i * 16;
            Ks[j][c4 + 0] = f2tf32(pk[i].x); Ks[j][c4 + 1] = f2tf32(pk[i].y);
            Ks[j][c4 + 2] = f2tf32(pk[i].z); Ks[j][c4 + 3] = f2tf32(pk[i].w);
            Vs[j][c4 + 0] = f2tf32(pv[i].x); Vs[j][c4 + 1] = f2tf32(pv[i].y);
            Vs[j][c4 + 2] = f2tf32(pv[i].z); Vs[j][c4 + 3] = f2tf32(pv[i].w);
        }
        // Issue gmem loads for the NEXT tile; latency overlaps compute below
        if (t0 + KT < Teff) PREFETCH(t0 + KT);
        __syncthreads();

        // ---- S = Q K^T ----
        float sc[4][4];
#pragma unroll
        for (int nf = 0; nf < 4; nf++) {
#pragma unroll
            for (int e = 0; e < 4; e++) sc[nf][e] = 0.f;
#pragma unroll
            for (int kk = 0; kk < 8; kk++) {
                uint32_t b0 = Ks[nf * 8 + lr][kk * 8 + lc];
                uint32_t b1 = Ks[nf * 8 + lr][kk * 8 + lc + 4];
                asm volatile(
                    "mma.sync.aligned.m16n8k8.row.col.f32.tf32.tf32.f32 "
                    "{%0,%1,%2,%3}, {%4,%5,%6,%7}, {%8,%9}, {%0,%1,%2,%3};"
                    : "+f"(sc[nf][0]), "+f"(sc[nf][1]),
                      "+f"(sc[nf][2]), "+f"(sc[nf][3])
                    : "r"(aq[kk][0]), "r"(aq[kk][1]),
                      "r"(aq[kk][2]), "r"(aq[kk][3]),
                      "r"(b0), "r"(b1));
            }
        }

        // ---- scale + mask; row max ----
        const bool need_mask = (t0 + KT > L);
        float mx_lo = NEG_INF, mx_hi = NEG_INF;
#pragma unroll
        for (int nf = 0; nf < 4; nf++) {
#pragma unroll
            for (int e = 0; e < 4; e++) {
                int t = t0 + nf * 8 + 2 * lc + (e & 1);
                float v = sc[nf][e] * 0.125f;
                if (need_mask) {
                    bool valid = (t < Teff);
                    if (valid && t >= L) {
                        int srow = s0 + lr + ((e >= 2) ? 8 : 0);
                        if (mask[((size_t)srow * QS + (t - L)) * BATCH + b]) valid = false;
                    }
                    v = valid ? v : NEG_INF;
                }
                sc[nf][e] = v;
                if (e < 2) mx_lo = fmaxf(mx_lo, v);
                else       mx_hi = fmaxf(mx_hi, v);
            }
        }
        mx_lo = fmaxf(mx_lo, __shfl_xor_sync(0xffffffffu, mx_lo, 1));
        mx_lo = fmaxf(mx_lo, __shfl_xor_sync(0xffffffffu, mx_lo, 2));
        mx_hi = fmaxf(mx_hi, __shfl_xor_sync(0xffffffffu, mx_hi, 1));
        mx_hi = fmaxf(mx_hi, __shfl_xor_sync(0xffffffffu, mx_hi, 2));

        const float mn_lo = fmaxf(m_lo, mx_lo);
        const float mn_hi = fmaxf(m_hi, mx_hi);
        const float corr_lo = (mn_lo > NEG_INF) ? __expf(m_lo - mn_lo) : 1.f;
        const float corr_hi = (mn_hi > NEG_INF) ? __expf(m_hi - mn_hi) : 1.f;

        float sum_lo = 0.f, sum_hi = 0.f;
#pragma unroll
        for (int nf = 0; nf < 4; nf++) {
            float p0 = (mn_lo > NEG_INF) ? __expf(sc[nf][0] - mn_lo) : 0.f;
            float p1 = (mn_lo > NEG_INF) ? __expf(sc[nf][1] - mn_lo) : 0.f;
            float p2 = (mn_hi > NEG_INF) ? __expf(sc[nf][2] - mn_hi) : 0.f;
            float p3 = (mn_hi > NEG_INF) ? __expf(sc[nf][3] - mn_hi) : 0.f;
            sum_lo += p0 + p1;
            sum_hi += p2 + p3;
            sc[nf][0] = p0; sc[nf][1] = p1; sc[nf][2] = p2; sc[nf][3] = p3;
        }
        sum_lo += __shfl_xor_sync(0xffffffffu, sum_lo, 1);
        sum_lo += __shfl_xor_sync(0xffffffffu, sum_lo, 2);
        sum_hi += __shfl_xor_sync(0xffffffffu, sum_hi, 1);
        sum_hi += __shfl_xor_sync(0xffffffffu, sum_hi, 2);

        l_lo = l_lo * corr_lo + sum_lo;
        l_hi = l_hi * corr_hi + sum_hi;
        m_lo = mn_lo; m_hi = mn_hi;

#pragma unroll
        for (int nf = 0; nf < 8; nf++) {
            O[nf][0] *= corr_lo; O[nf][1] *= corr_lo;
            O[nf][2] *= corr_hi; O[nf][3] *= corr_hi;
        }

        // ---- P (C-frag) -> smem -> A-frag ----
#pragma unroll
        for (int nf = 0; nf < 4; nf++) {
            Pw[warp][lr][nf * 8 + 2 * lc]         = f2tf32(sc[nf][0]);
            Pw[warp][lr][nf * 8 + 2 * lc + 1]     = f2tf32(sc[nf][1]);
            Pw[warp][lr + 8][nf * 8 + 2 * lc]     = f2tf32(sc[nf][2]);
            Pw[warp][lr + 8][nf * 8 + 2 * lc + 1] = f2tf32(sc[nf][3]);
        }
        __syncwarp();
        uint32_t ap[4][4];
#pragma unroll
        for (int kk = 0; kk < 4; kk++) {
            ap[kk][0] = Pw[warp][lr][kk * 8 + lc];
            ap[kk][1] = Pw[warp][lr + 8][kk * 8 + lc];
            ap[kk][2] = Pw[warp][lr][kk * 8 + lc + 4];
            ap[kk][3] = Pw[warp][lr + 8][kk * 8 + lc + 4];
        }
        __syncwarp();

        // ---- O += P V ----
#pragma unroll
        for (int nf = 0; nf < 8; nf++) {
#pragma unroll
            for (int kk = 0; kk < 4; kk++) {
                uint32_t b0 = Vs[kk * 8 + lc][nf * 8 + lr];
                uint32_t b1 = Vs[kk * 8 + lc + 4][nf * 8 + lr];
                asm volatile(
                    "mma.sync.aligned.m16n8k8.row.col.f32.tf32.tf32.f32 "
                    "{%0,%1,%2,%3}, {%4,%5,%6,%7}, {%8,%9}, {%0,%1,%2,%3};"
                    : "+f"(O[nf][0]), "+f"(O[nf][1]),
                      "+f"(O[nf][2]), "+f"(O[nf][3])
                    : "r"(ap[kk][0]), "r"(ap[kk][1]),
                      "r"(ap[kk][2]), "r"(ap[kk][3]),
                      "r"(b0), "r"(b1));
            }
        }
    }
#undef PREFETCH

    // Epilogue: normalize, round to tf32 (feeds O-proj GEMM directly), store.
    const float inv_lo = (l_lo > 0.f) ? (1.f / l_lo) : 0.f;
    const float inv_hi = (l_hi > 0.f) ? (1.f / l_hi) : 0.f;
    float* xlo = X + ((size_t)(s0 + lr) * BATCH + b) * CDIM + h * HC;
    float* xhi = xlo + (size_t)8 * BATCH * CDIM;
#pragma unroll
    for (int nf = 0; nf < 8; nf++) {
        int c = nf * 8 + 2 * lc;
        *(float2*)(xlo + c) = make_float2(
            __uint_as_float(f2tf32(O[nf][0] * inv_lo)),
            __uint_as_float(f2tf32(O[nf][1] * inv_lo)));
        *(float2*)(xhi + c) = make_float2(
            __uint_as_float(f2tf32(O[nf][2] * inv_hi)),
            __uint_as_float(f2tf32(O[nf][3] * inv_hi)));
    }
}

// ---------------------------------------------------------------------------
// Launch: pre-round -> QKV GEMM (pipelined) -> attention -> O GEMM.
// Input order: xq, pad, mask, memory_length, memory_kv,
//              Wq, bq, Wk, bk, Wv, bv, Wo, bo
// ---------------------------------------------------------------------------
extern "C" void kernel_launch(void* const* d_in, const int* in_sizes, int n_in,
                              void* d_out, int out_size)
{
    const float*         xq     = (const float*)d_in[0];
    const int*           padv   = (const int*)d_in[1];
    const unsigned char* mask   = (const unsigned char*)d_in[2];
    const int*           memlen = (const int*)d_in[3];
    const float*         memkv  = (const float*)d_in[4];
    const float*         Wq     = (const float*)d_in[5];
    const float*         bq     = (const float*)d_in[6];
    const float*         Wk     = (const float*)d_in[7];
    const float*         bk     = (const float*)d_in[8];
    const float*         Wv     = (const float*)d_in[9];
    const float*         bv     = (const float*)d_in[10];
    const float*         Wo     = (const float*)d_in[11];
    const float*         bo     = (const float*)d_in[12];
    float*               out    = (float*)d_out;

    float *qb, *kb, *vb, *xb, *xqt, *wt;
    cudaGetSymbolAddress((void**)&qb,  g_qbuf);
    cudaGetSymbolAddress((void**)&kb,  g_kbuf);
    cudaGetSymbolAddress((void**)&vb,  g_vbuf);
    cudaGetSymbolAddress((void**)&xb,  g_xbuf);
    cudaGetSymbolAddress((void**)&xqt, g_xqt);
    cudaGetSymbolAddress((void**)&wt,  g_wt);

    const int GEMM_SMEM = 2 * 2 * 128 * 36 * 4;   // 73728 B
    (void)cudaFuncSetAttribute(gemm_tf32_pipe,
                               cudaFuncAttributeMaxDynamicSharedMemorySize,
                               GEMM_SMEM);

    // Pre-round xq and weights to tf32 (rna)
    round_tf32_multi<<<dim3(1024, 5), 256>>>(xq, Wq, Wk, Wv, Wo, xqt, wt);

    GemmSet sq{wt,                 bq, qb};
    GemmSet sk{wt + CDIM * CDIM,   bk, kb};
    GemmSet sv{wt + 2*CDIM*CDIM,   bv, vb};
    GemmSet so{wt + 3*CDIM*CDIM,   bo, out};

    // Fused QKV projection: M=4096, N=3*1024, K=1024
    gemm_tf32_pipe<<<dim3(32, 24), 256, GEMM_SMEM>>>(xqt, sq, sk, sv);

    // Attention: 4 q-tiles x (B*H=128)
    attn_mma<<<dim3(4, 128), 256>>>(qb, kb, vb, memkv, memlen, padv, mask, xb);

    // Output projection: M=4096, N=1024, K=1024
    gemm_tf32_pipe<<<dim3(32, 8), 256, GEMM_SMEM>>>(xb, so, so, so);
}